// round 9
// baseline (speedup 1.0000x reference)
#include <cuda_runtime.h>
#include <cuda_bf16.h>
#include <cstdint>
#include <math.h>

// GRU: T=512, B=64, H=I=1024
// - x-projections: 3-term bf16-split GEMM, 128x128 tiles, all 3 terms per
//   K-slab load (A/B hi+lo resident per iteration)
// - recurrence: ONE persistent kernel, 64 CTAs x 512 threads (16 warps),
//   weights resident in SMEM, A-tiles broadcast via cp.async.bulk + mbarrier,
//   red.release/ld.acquire grid barrier (2/step), MUFU activations,
//   2 independent accumulator chains per warp (HMMA latency hiding).

#define Tn 512
#define Bn 64
#define Hn 1024
#define In 1024
#define HIn 2048
#define Mtot (Tn * Bn)   // 32768
#define GRID_P 64

typedef __nv_bfloat16 bf16;

// ---------------- device globals (no runtime allocation allowed) ----------
__device__ __align__(256) bf16  g_Wh[6ull * Hn * Hn];     // [z hi,lo | r hi,lo | t hi,lo][n][k]
__device__ __align__(256) bf16  g_Wx[6ull * Hn * In];
__device__ __align__(256) bf16  g_xh[(size_t)Mtot * In];
__device__ __align__(256) bf16  g_xl[(size_t)Mtot * In];
__device__ __align__(256) float g_xpre[3ull * Mtot * Hn]; // x@Wx^T + b per gate
__device__ __align__(256) float g_h[Bn * Hn];
__device__ __align__(256) float g_z[Bn * Hn];
// A tiles, pre-swizzled tile-contiguous: [16 kt][2 split][64 rows][128B swz]
__device__ __align__(256) bf16  g_A1[2 * Bn * Hn];        // h splits
__device__ __align__(256) bf16  g_A2[2 * Bn * Hn];        // (r*h) splits
__device__ unsigned g_arrive;

// byte offset of element (row, col) inside a [kt][split=0] plane of g_A1/g_A2
__device__ __forceinline__ size_t aoff(int row, int col) {
    int kt = col >> 6, cg = (col >> 3) & 7, c8 = col & 7;
    return (size_t)kt * 16384 + (size_t)row * 128 + (((cg ^ (row & 7)) << 4) + c8 * 2);
}

// ---------------- helpers ----------------
__device__ __forceinline__ void split2(float v, bf16& hi, bf16& lo) {
    hi = __float2bfloat16(v);
    lo = __float2bfloat16(v - __bfloat162float(hi));
}
__device__ __forceinline__ float sigmoid_f(float x) {
    return 1.f / (1.f + __expf(-x));
}
__device__ __forceinline__ float tanh_f(float x) {
    return 1.f - 2.f / (__expf(2.f * x) + 1.f);
}
__device__ __forceinline__ void cp16(void* s, const void* g) {
    uint32_t sa = (uint32_t)__cvta_generic_to_shared(s);
    asm volatile("cp.async.ca.shared.global [%0], [%1], 16;\n" :: "r"(sa), "l"(g));
}
#define CP_COMMIT() asm volatile("cp.async.commit_group;\n")
#define CP_WAIT1()  asm volatile("cp.async.wait_group 1;\n")
#define CP_WAIT0()  asm volatile("cp.async.wait_group 0;\n")

__device__ __forceinline__ void mma16816(float* c, const uint32_t* a, const uint32_t* b) {
    asm volatile(
        "mma.sync.aligned.m16n8k16.row.col.f32.bf16.bf16.f32 "
        "{%0,%1,%2,%3}, {%4,%5,%6,%7}, {%8,%9}, {%0,%1,%2,%3};\n"
        : "+f"(c[0]), "+f"(c[1]), "+f"(c[2]), "+f"(c[3])
        : "r"(a[0]), "r"(a[1]), "r"(a[2]), "r"(a[3]), "r"(b[0]), "r"(b[1]));
}
__device__ __forceinline__ void ldsm4(uint32_t* r, const void* p) {
    uint32_t a = (uint32_t)__cvta_generic_to_shared(p);
    asm volatile("ldmatrix.sync.aligned.m8n8.x4.shared.b16 {%0,%1,%2,%3}, [%4];\n"
                 : "=r"(r[0]), "=r"(r[1]), "=r"(r[2]), "=r"(r[3]) : "r"(a));
}
__device__ __forceinline__ void ldsm2(uint32_t* r, const void* p) {
    uint32_t a = (uint32_t)__cvta_generic_to_shared(p);
    asm volatile("ldmatrix.sync.aligned.m8n8.x2.shared.b16 {%0,%1}, [%2];\n"
                 : "=r"(r[0]), "=r"(r[1]) : "r"(a));
}
__device__ __forceinline__ void mbar_wait(uint32_t mbar, unsigned parity) {
    asm volatile(
        "{\n\t.reg .pred P;\n"
        "W%=:\n\tmbarrier.try_wait.parity.acquire.cta.shared::cta.b64 P, [%0], %1, 0x989680;\n"
        "\t@P bra D%=;\n"
        "\tbra W%=;\n"
        "D%=:\n\t}\n"
        :: "r"(mbar), "r"(parity) : "memory");
}

// software grid barrier (all GRID_P CTAs resident: 1 CTA/SM by smem)
// non-serializing arrival: red.release (one-way) + ld.acquire poll by leader.
__device__ __forceinline__ void grid_bar(unsigned target) {
    __threadfence();
    __syncthreads();
    if (threadIdx.x == 0) {
        asm volatile("red.release.gpu.global.add.u32 [%0], 1;" :: "l"(&g_arrive) : "memory");
        unsigned v;
        do {
            asm volatile("ld.acquire.gpu.global.u32 %0, [%1];" : "=r"(v) : "l"(&g_arrive));
        } while (v < target);
    }
    __syncthreads();
}

// ---------------- prep kernels ----------------
__global__ void prep_weights(const float* Wz, const float* Wr, const float* Wt) {
    int total = 3 * Hn * HIn;
    for (int i = blockIdx.x * blockDim.x + threadIdx.x; i < total; i += gridDim.x * blockDim.x) {
        int g = i / (Hn * HIn);
        int rem = i - g * (Hn * HIn);
        int n = rem / HIn, k = rem - n * HIn;
        const float* W = (g == 0) ? Wz : ((g == 1) ? Wr : Wt);
        float v = W[(size_t)n * HIn + k];
        bf16 hi, lo; split2(v, hi, lo);
        if (k < Hn) {
            g_Wh[(size_t)(g * 2)     * Hn * Hn + (size_t)n * Hn + k] = hi;
            g_Wh[(size_t)(g * 2 + 1) * Hn * Hn + (size_t)n * Hn + k] = lo;
        } else {
            int kk = k - Hn;
            g_Wx[(size_t)(g * 2)     * Hn * In + (size_t)n * In + kk] = hi;
            g_Wx[(size_t)(g * 2 + 1) * Hn * In + (size_t)n * In + kk] = lo;
        }
    }
}
__global__ void prep_x(const float* x) {
    size_t total = (size_t)Mtot * In;
    size_t stride = (size_t)gridDim.x * blockDim.x;
    for (size_t i = blockIdx.x * (size_t)blockDim.x + threadIdx.x; i < total; i += stride) {
        bf16 hi, lo; split2(x[i], hi, lo);
        g_xh[i] = hi; g_xl[i] = lo;
    }
}
__global__ void prep_h(const float* h0) {
    int i = blockIdx.x * blockDim.x + threadIdx.x;
    if (i == 0) g_arrive = 0;                 // reset barrier counter each launch/replay
    if (i < Bn * Hn) {
        float v = h0[i];
        g_h[i] = v;
        bf16 hi, lo; split2(v, hi, lo);
        int row = i >> 10, col = i & (Hn - 1);
        char* p = (char*)g_A1 + aoff(row, col);
        *(bf16*)p = hi;
        *(bf16*)(p + 8192) = lo;
    }
}

// ---------------- x-projection GEMM (3-term split, 128x128 tiles) ----------
// 32 K-slab iterations; each loads Ah, Al, Bh, Bl (128x32 bf16 each) and does
// all 3 split terms (hh, hl, lh). Dynamic smem: 4 tiles x 2 buf x 10240 B.
#define LDS_PAD 40
#define XT 10240
__device__ __forceinline__ void ldAfrag(uint32_t* a, const bf16* As, int mb, int k0, int lane) {
    int r = lane >> 2, c2 = (lane & 3) * 2;
    a[0] = *(const uint32_t*)(As + (size_t)(mb + r)     * LDS_PAD + k0 + c2);
    a[1] = *(const uint32_t*)(As + (size_t)(mb + r + 8) * LDS_PAD + k0 + c2);
    a[2] = *(const uint32_t*)(As + (size_t)(mb + r)     * LDS_PAD + k0 + 8 + c2);
    a[3] = *(const uint32_t*)(As + (size_t)(mb + r + 8) * LDS_PAD + k0 + 8 + c2);
}
__device__ __forceinline__ void ldBfrag(uint32_t* b, const bf16* Bs, int nb, int k0, int lane) {
    int r = lane >> 2, c2 = (lane & 3) * 2;
    b[0] = *(const uint32_t*)(Bs + (size_t)(nb + r) * LDS_PAD + k0 + c2);
    b[1] = *(const uint32_t*)(Bs + (size_t)(nb + r) * LDS_PAD + k0 + 8 + c2);
}

// grid (24 = gate*8 + ntile, 256 = mtile). CTA tile 128x128, BK=32, 32 iters.
__global__ void __launch_bounds__(256) xproj_kernel(const float* bz, const float* br, const float* bt) {
    extern __shared__ char xsm[];
    const int gate = blockIdx.x >> 3;
    const int n0 = (blockIdx.x & 7) * 128;
    const int m0 = blockIdx.y * 128;
    const int tid = threadIdx.x, lane = tid & 31, warp = tid >> 5;
    const int wm = (warp & 3) * 32, wn = (warp >> 2) * 64;

    const bf16* Bh0 = g_Wx + (size_t)(gate * 2)     * ((size_t)Hn * In) + (size_t)n0 * In;
    const bf16* Bl0 = g_Wx + (size_t)(gate * 2 + 1) * ((size_t)Hn * In) + (size_t)n0 * In;

    float acc[2][8][4];
    #pragma unroll
    for (int i = 0; i < 2; i++)
        #pragma unroll
        for (int j = 0; j < 8; j++)
            #pragma unroll
            for (int k = 0; k < 4; k++) acc[i][j][k] = 0.f;

    auto issue = [&](int it, int buf) {
        int kk = it * 32;
        #pragma unroll
        for (int j = 0; j < 2; j++) {
            int id = tid + j * 256;
            int r = id >> 2, cg = (id & 3) * 8;
            size_t go = (size_t)r * In + kk + cg;
            char* base = xsm + (size_t)buf * (4 * XT) + (r * LDS_PAD + cg) * 2;
            cp16(base,           g_xh + (size_t)(m0) * In + go);
            cp16(base + XT,      g_xl + (size_t)(m0) * In + go);
            cp16(base + 2 * XT,  Bh0 + go);
            cp16(base + 3 * XT,  Bl0 + go);
        }
    };

    issue(0, 0);
    CP_COMMIT();
    for (int it = 0; it < 32; it++) {
        int buf = it & 1;
        if (it + 1 < 32) { issue(it + 1, buf ^ 1); CP_COMMIT(); CP_WAIT1(); }
        else             { CP_WAIT0(); }
        __syncthreads();
        const bf16* Ah = (const bf16*)(xsm + (size_t)buf * (4 * XT));
        const bf16* Al = (const bf16*)(xsm + (size_t)buf * (4 * XT) + XT);
        const bf16* Bh = (const bf16*)(xsm + (size_t)buf * (4 * XT) + 2 * XT);
        const bf16* Bl = (const bf16*)(xsm + (size_t)buf * (4 * XT) + 3 * XT);
        #pragma unroll
        for (int ks = 0; ks < 32; ks += 16) {
            uint32_t ah[2][4], al[2][4];
            #pragma unroll
            for (int mi = 0; mi < 2; mi++) {
                ldAfrag(ah[mi], Ah, wm + mi * 16, ks, lane);
                ldAfrag(al[mi], Al, wm + mi * 16, ks, lane);
            }
            #pragma unroll
            for (int half = 0; half < 2; half++) {
                uint32_t bhf[4][2], blf[4][2];
                #pragma unroll
                for (int nf = 0; nf < 4; nf++) {
                    ldBfrag(bhf[nf], Bh, wn + half * 32 + nf * 8, ks, lane);
                    ldBfrag(blf[nf], Bl, wn + half * 32 + nf * 8, ks, lane);
                }
                #pragma unroll
                for (int mi = 0; mi < 2; mi++)
                    #pragma unroll
                    for (int nf = 0; nf < 4; nf++) {
                        float* a4 = acc[mi][half * 4 + nf];
                        mma16816(a4, ah[mi], bhf[nf]);
                        mma16816(a4, ah[mi], blf[nf]);
                        mma16816(a4, al[mi], bhf[nf]);
                    }
            }
        }
        __syncthreads();
    }

    const float* bias = (gate == 0) ? bz : ((gate == 1) ? br : bt);
    #pragma unroll
    for (int mi = 0; mi < 2; mi++) {
        #pragma unroll
        for (int nf = 0; nf < 8; nf++) {
            int row = m0 + wm + mi * 16 + (lane >> 2);
            int col = n0 + wn + nf * 8 + (lane & 3) * 2;
            float b0v = bias[col], b1v = bias[col + 1];
            size_t base = (size_t)gate * Mtot * Hn + (size_t)row * Hn + col;
            g_xpre[base]              = acc[mi][nf][0] + b0v;
            g_xpre[base + 1]          = acc[mi][nf][1] + b1v;
            g_xpre[base + 8 * Hn]     = acc[mi][nf][2] + b0v;
            g_xpre[base + 8 * Hn + 1] = acc[mi][nf][3] + b1v;
        }
    }
}

// ---------------- persistent recurrence kernel ----------------
// 64 CTAs x 512 threads (16 warps). CTA nt owns cols [nt*16, nt*16+16).
// SMEM: sWzr [2 split][32 rows (0-15=z, 16-31=r)][1024]  = 131072 B
//       sWt  [2 split][16 rows][1024]                    =  65536 B
//       sA   [2 buf][2 split][64 rows][64 k]             =  32768 B (scratch-reused)
//       mbar [2]                                         =     16 B
#define WZR_OFF 0
#define WT_OFF  131072
#define SA_OFF  196608
#define MB_OFF  229376
#define SMEM_P  229440

__global__ void __launch_bounds__(512, 1) gru_persistent(float* __restrict__ out) {
    extern __shared__ char smem[];
    const int tid = threadIdx.x, lane = tid & 31, warp = tid >> 5;
    const int nt = blockIdx.x;
    const int wm = (warp & 3) * 16;      // warp row base (M=64 over 4 row-groups)
    const int cg4 = warp >> 2;           // 0..3: phase1 col group (8 cols each)
    const int kgrp = warp >> 3;          // 0..1: phase2 ks group

    const uint32_t smem_u32 = (uint32_t)__cvta_generic_to_shared(smem);
    const uint32_t sa_u32 = smem_u32 + SA_OFF;
    const uint32_t mb_u32 = smem_u32 + MB_OFF;
    float* scratch = (float*)(smem + SA_OFF);   // 64x16 f32, reused after phase2 loop

    // ---- load resident weights into SMEM (once) ----
    #pragma unroll
    for (int j = 0; j < 16; j++) {       // sWzr: 8192 x 16B chunks
        int id = tid + j * 512;
        int split = id >> 12, row = (id >> 7) & 31, c = id & 127;
        int gidx = (row < 16 ? 0 : 2) + split;
        const bf16* src = g_Wh + ((size_t)gidx << 20) + (size_t)(nt * 16 + (row & 15)) * 1024 + c * 8;
        int csw = (c & 0x78) | ((c ^ row) & 7);
        cp16(smem + WZR_OFF + split * 65536 + row * 2048 + csw * 16, src);
    }
    #pragma unroll
    for (int j = 0; j < 8; j++) {        // sWt: 4096 chunks
        int id = tid + j * 512;
        int split = id >> 11, row = (id >> 7) & 15, c = id & 127;
        const bf16* src = g_Wh + ((size_t)(4 + split) << 20) + (size_t)(nt * 16 + row) * 1024 + c * 8;
        int csw = (c & 0x78) | ((c ^ row) & 7);
        cp16(smem + WT_OFF + split * 32768 + row * 2048 + csw * 16, src);
    }
    CP_COMMIT(); CP_WAIT0();
    if (tid == 0) {
        asm volatile("mbarrier.init.shared.b64 [%0], 1;" :: "r"(mb_u32) : "memory");
        asm volatile("mbarrier.init.shared.b64 [%0], 1;" :: "r"(mb_u32 + 8) : "memory");
    }
    __syncthreads();

    // per-lane fragment address components
    const int arow = wm + (lane & 15);                       // A row for ldsm x4
    const int bn1  = cg4 * 8 + (lane & 7);                   // phase1 B smem row (0..31)
    const int bn2  = (cg4 & 1) * 8 + (lane & 7);             // phase2 B smem row (0..15)
    const int bkh  = ((lane >> 3) & 1) * 8;                  // B k-half

    // per-lane epilogue element coordinates (c-fragment layout)
    int erow[4], ecol[4];
    #pragma unroll
    for (int e = 0; e < 4; e++) {
        erow[e] = wm + (lane >> 2) + ((e >> 1) * 8);
        ecol[e] = (lane & 3) * 2 + (e & 1);
    }

    // one 16KB bulk copy brings k-tile kt (both splits) into sA[buf]
    auto issue_tile = [&](const char* gbase, int kt, int buf) {
        if (tid == 0) {
            uint32_t mb = mb_u32 + buf * 8;
            asm volatile("mbarrier.arrive.expect_tx.shared.b64 _, [%0], %1;"
                         :: "r"(mb), "r"(16384) : "memory");
            asm volatile(
                "cp.async.bulk.shared::cluster.global.mbarrier::complete_tx::bytes [%0], [%1], %2, [%3];"
                :: "r"(sa_u32 + buf * 16384), "l"(gbase + (size_t)kt * 16384),
                   "r"(16384), "r"(mb) : "memory");
        }
    };

    unsigned p0 = 0, p1 = 0;             // mbarrier phase parity per buffer
    unsigned bt = 0;
    for (int t = 0; t < Tn; t++) {
        // ================= phase 1: pre_{z,r} = h @ Wzr^T =================
        // 16 warps: 4 row-groups x 4 col-groups (cols 0-15 z, 16-31 r), m16n8 each.
        // Two accumulator chains per warp: [0]=hh term, [1]=cross terms.
        float acc1[2][4];
        #pragma unroll
        for (int i = 0; i < 2; i++)
            #pragma unroll
            for (int j = 0; j < 4; j++) acc1[i][j] = 0.f;
        issue_tile((const char*)g_A1, 0, 0);

        // prefetch epilogue operands (own-CTA cols)
        const int gate1 = (cg4 < 2) ? 0 : 1;       // z or r
        const int lcol1 = (cg4 & 1) * 8;           // local col base within 16
        float xp1[4], hpre[4];
        #pragma unroll
        for (int e = 0; e < 4; e++) {
            int col = nt * 16 + lcol1 + ecol[e];
            size_t xoff = ((size_t)gate1 * Mtot + (size_t)t * Bn + erow[e]) * Hn + col;
            xp1[e] = g_xpre[xoff];
            if (gate1) hpre[e] = g_h[erow[e] * Hn + col];
        }

        for (int kt = 0; kt < 16; kt++) {
            int buf = kt & 1;
            if (kt + 1 < 16) issue_tile((const char*)g_A1, kt + 1, buf ^ 1);
            if (buf == 0) { mbar_wait(mb_u32, p0); p0 ^= 1; }
            else         { mbar_wait(mb_u32 + 8, p1); p1 ^= 1; }
            #pragma unroll
            for (int ks = 0; ks < 4; ks++) {
                int kl = ks * 16 + (lane >> 4) * 8;
                const char* pA = smem + SA_OFF + buf * 16384 + arow * 128 + (((kl >> 3) ^ (arow & 7)) << 4);
                uint32_t ah[4], al[4];
                ldsm4(ah, pA); ldsm4(al, pA + 8192);
                int kg = kt * 64 + ks * 16 + bkh;
                const char* pB = smem + WZR_OFF + bn1 * 2048 + (((kg >> 3) ^ (bn1 & 7)) << 4);
                uint32_t bh[2], bl[2];
                ldsm2(bh, pB); ldsm2(bl, pB + 65536);
                mma16816(acc1[0], ah, bh);
                mma16816(acc1[1], ah, bl);
                mma16816(acc1[1], al, bh);
            }
            __syncthreads();
        }

        // ---- act1: z -> g_z ; r -> (r*h) splits into g_A2 ----
        #pragma unroll
        for (int e = 0; e < 4; e++) {
            int col = nt * 16 + lcol1 + ecol[e];
            float s = sigmoid_f(acc1[0][e] + acc1[1][e] + xp1[e]);
            if (gate1) {          // r-warps
                float rh = s * hpre[e];
                bf16 hi, lo; split2(rh, hi, lo);
                char* p = (char*)g_A2 + aoff(erow[e], col);
                *(bf16*)p = hi;
                *(bf16*)(p + 8192) = lo;
            } else {              // z-warps
                g_z[erow[e] * Hn + col] = s;
            }
        }
        bt += GRID_P; grid_bar(bt);

        // ================= phase 2: pre_t = (r*h) @ Wt^T =================
        // 16 warps: 4 row-groups x 2 col-groups x 2 ks-groups; reduce in smem.
        float acc2[2][4];
        #pragma unroll
        for (int i = 0; i < 2; i++)
            #pragma unroll
            for (int j = 0; j < 4; j++) acc2[i][j] = 0.f;
        issue_tile((const char*)g_A2, 0, 0);

        const int lcol2 = (cg4 & 1) * 8;
        float xp2[4], zpre[4], hpre2[4];
        if (kgrp == 0) {
            #pragma unroll
            for (int e = 0; e < 4; e++) {
                int col = nt * 16 + lcol2 + ecol[e];
                size_t xoff = (2ull * Mtot + (size_t)t * Bn + erow[e]) * Hn + col;
                xp2[e] = g_xpre[xoff];
                int gi = erow[e] * Hn + col;
                zpre[e] = g_z[gi];
                hpre2[e] = g_h[gi];
            }
        }

        for (int kt = 0; kt < 16; kt++) {
            int buf = kt & 1;
            if (kt + 1 < 16) issue_tile((const char*)g_A2, kt + 1, buf ^ 1);
            if (buf == 0) { mbar_wait(mb_u32, p0); p0 ^= 1; }
            else         { mbar_wait(mb_u32 + 8, p1); p1 ^= 1; }
            #pragma unroll
            for (int kss = 0; kss < 2; kss++) {
                int ks = kgrp * 2 + kss;
                int kl = ks * 16 + (lane >> 4) * 8;
                const char* pA = smem + SA_OFF + buf * 16384 + arow * 128 + (((kl >> 3) ^ (arow & 7)) << 4);
                uint32_t ah[4], al[4];
                ldsm4(ah, pA); ldsm4(al, pA + 8192);
                int kg = kt * 64 + ks * 16 + bkh;
                const char* pB = smem + WT_OFF + bn2 * 2048 + (((kg >> 3) ^ (bn2 & 7)) << 4);
                uint32_t bh[2], bl[2];
                ldsm2(bh, pB); ldsm2(bl, pB + 32768);
                mma16816(acc2[0], ah, bh);
                mma16816(acc2[1], ah, bl);
                mma16816(acc2[1], al, bh);
            }
            __syncthreads();
        }

        // ---- reduce ks-groups, then act2: h update + output ----
        if (kgrp == 1) {
            #pragma unroll
            for (int e = 0; e < 4; e++)
                scratch[erow[e] * 16 + lcol2 + ecol[e]] = acc2[0][e] + acc2[1][e];
        }
        __syncthreads();
        if (kgrp == 0) {
            #pragma unroll
            for (int e = 0; e < 4; e++) {
                int col = nt * 16 + lcol2 + ecol[e];
                float pre = acc2[0][e] + acc2[1][e] + scratch[erow[e] * 16 + lcol2 + ecol[e]] + xp2[e];
                float ht = tanh_f(pre);
                int gi = erow[e] * Hn + col;
                float z = zpre[e];
                float hn = (1.f - z) * hpre2[e] + z * ht;
                g_h[gi] = hn;
                bf16 hi, lo; split2(hn, hi, lo);
                char* p = (char*)g_A1 + aoff(erow[e], col);
                *(bf16*)p = hi;
                *(bf16*)(p + 8192) = lo;
                out[(size_t)t * (Bn * Hn) + gi] = hn;
            }
        }
        bt += GRID_P; grid_bar(bt);
    }
}

// ---------------- launch ----------------
extern "C" void kernel_launch(void* const* d_in, const int* in_sizes, int n_in,
                              void* d_out, int out_size) {
    const float* x    = (const float*)d_in[0];
    const float* h0   = (const float*)d_in[1];
    const float* Wz_w = (const float*)d_in[2];
    const float* Wz_b = (const float*)d_in[3];
    const float* Wr_w = (const float*)d_in[4];
    const float* Wr_b = (const float*)d_in[5];
    const float* Wt_w = (const float*)d_in[6];
    const float* Wt_b = (const float*)d_in[7];
    float* out = (float*)d_out;

    cudaFuncSetAttribute(gru_persistent, cudaFuncAttributeMaxDynamicSharedMemorySize, SMEM_P);
    cudaFuncSetAttribute(xproj_kernel, cudaFuncAttributeMaxDynamicSharedMemorySize, 8 * XT);

    prep_weights<<<3072, 256>>>(Wz_w, Wr_w, Wt_w);
    prep_x<<<8192, 256>>>(x);
    prep_h<<<(Bn * Hn + 255) / 256, 256>>>(h0);
    xproj_kernel<<<dim3(24, 256), 256, 8 * XT>>>(Wz_b, Wr_b, Wt_b);
    gru_persistent<<<GRID_P, 512, SMEM_P>>>(out);
}

// round 12
// speedup vs baseline: 1.0798x; 1.0798x over previous
#include <cuda_runtime.h>
#include <cuda_bf16.h>
#include <cstdint>
#include <math.h>

// GRU: T=512, B=64, H=I=1024
// Recurrence: ONE persistent kernel, 64 CTAs = 16 N-groups x 4 K-chunks.
// Each CTA: resident weight slice (196KB), 4 A-tile iterations per phase
// (K-split), fp32 partials in global, acts sum 4 partials. 4 grid barriers
// per step (red.release + ld.acquire). A-tiles broadcast via cp.async.bulk.

#define Tn 512
#define Bn 64
#define Hn 1024
#define In 1024
#define HIn 2048
#define Mtot (Tn * Bn)   // 32768
#define GRID_P 64

typedef __nv_bfloat16 bf16;

// ---------------- device globals ----------------
__device__ __align__(256) bf16  g_Wh[6ull * Hn * Hn];     // [z hi,lo | r hi,lo | t hi,lo][n][k]
__device__ __align__(256) bf16  g_Wx[6ull * Hn * In];
__device__ __align__(256) bf16  g_xh[(size_t)Mtot * In];
__device__ __align__(256) bf16  g_xl[(size_t)Mtot * In];
__device__ __align__(256) float g_xpre[3ull * Mtot * Hn]; // x@Wx^T + b per gate
__device__ __align__(256) float g_h[Bn * Hn];
__device__ __align__(256) float g_z[Bn * Hn];
// A tiles, pre-swizzled tile-contiguous: [16 kt][2 split][64 rows][128B swz]
__device__ __align__(256) bf16  g_A1[2 * Bn * Hn];        // h splits
__device__ __align__(256) bf16  g_A2[2 * Bn * Hn];        // (r*h) splits
// K-split partial buffers (fp32)
__device__ __align__(256) float g_p1[4 * Bn * HIn];       // [kc][64][2048]
__device__ __align__(256) float g_p2[4 * Bn * Hn];        // [kc][64][1024]
__device__ unsigned g_arrive;

// byte offset of element (row, col) inside a [kt][split=0] plane of g_A1/g_A2
__device__ __forceinline__ size_t aoff(int row, int col) {
    int kt = col >> 6, cg = (col >> 3) & 7, c8 = col & 7;
    return (size_t)kt * 16384 + (size_t)row * 128 + (((cg ^ (row & 7)) << 4) + c8 * 2);
}

// ---------------- helpers ----------------
__device__ __forceinline__ void split2(float v, bf16& hi, bf16& lo) {
    hi = __float2bfloat16(v);
    lo = __float2bfloat16(v - __bfloat162float(hi));
}
__device__ __forceinline__ float sigmoid_f(float x) {
    return 1.f / (1.f + __expf(-x));
}
__device__ __forceinline__ float tanh_f(float x) {
    return 1.f - 2.f / (__expf(2.f * x) + 1.f);
}
__device__ __forceinline__ void cp16(void* s, const void* g) {
    uint32_t sa = (uint32_t)__cvta_generic_to_shared(s);
    asm volatile("cp.async.ca.shared.global [%0], [%1], 16;\n" :: "r"(sa), "l"(g));
}
#define CP_COMMIT() asm volatile("cp.async.commit_group;\n")
#define CP_WAIT1()  asm volatile("cp.async.wait_group 1;\n")
#define CP_WAIT0()  asm volatile("cp.async.wait_group 0;\n")

__device__ __forceinline__ void mma16816(float* c, const uint32_t* a, const uint32_t* b) {
    asm volatile(
        "mma.sync.aligned.m16n8k16.row.col.f32.bf16.bf16.f32 "
        "{%0,%1,%2,%3}, {%4,%5,%6,%7}, {%8,%9}, {%0,%1,%2,%3};\n"
        : "+f"(c[0]), "+f"(c[1]), "+f"(c[2]), "+f"(c[3])
        : "r"(a[0]), "r"(a[1]), "r"(a[2]), "r"(a[3]), "r"(b[0]), "r"(b[1]));
}
__device__ __forceinline__ void ldsm4(uint32_t* r, const void* p) {
    uint32_t a = (uint32_t)__cvta_generic_to_shared(p);
    asm volatile("ldmatrix.sync.aligned.m8n8.x4.shared.b16 {%0,%1,%2,%3}, [%4];\n"
                 : "=r"(r[0]), "=r"(r[1]), "=r"(r[2]), "=r"(r[3]) : "r"(a));
}
__device__ __forceinline__ void mbar_wait(uint32_t mbar, unsigned parity) {
    asm volatile(
        "{\n\t.reg .pred P;\n"
        "W%=:\n\tmbarrier.try_wait.parity.acquire.cta.shared::cta.b64 P, [%0], %1, 0x989680;\n"
        "\t@P bra D%=;\n"
        "\tbra W%=;\n"
        "D%=:\n\t}\n"
        :: "r"(mbar), "r"(parity) : "memory");
}

// software grid barrier (64 CTAs, all resident: 1 CTA/SM by smem)
__device__ __forceinline__ void grid_bar(unsigned target) {
    __threadfence();
    __syncthreads();
    if (threadIdx.x == 0) {
        asm volatile("red.release.gpu.global.add.u32 [%0], 1;" :: "l"(&g_arrive) : "memory");
        unsigned v;
        do {
            asm volatile("ld.acquire.gpu.global.u32 %0, [%1];" : "=r"(v) : "l"(&g_arrive));
        } while (v < target);
    }
    __syncthreads();
}

// ---------------- prep kernels ----------------
__global__ void prep_weights(const float* Wz, const float* Wr, const float* Wt) {
    int total = 3 * Hn * HIn;
    for (int i = blockIdx.x * blockDim.x + threadIdx.x; i < total; i += gridDim.x * blockDim.x) {
        int g = i / (Hn * HIn);
        int rem = i - g * (Hn * HIn);
        int n = rem / HIn, k = rem - n * HIn;
        const float* W = (g == 0) ? Wz : ((g == 1) ? Wr : Wt);
        float v = W[(size_t)n * HIn + k];
        bf16 hi, lo; split2(v, hi, lo);
        if (k < Hn) {
            g_Wh[(size_t)(g * 2)     * Hn * Hn + (size_t)n * Hn + k] = hi;
            g_Wh[(size_t)(g * 2 + 1) * Hn * Hn + (size_t)n * Hn + k] = lo;
        } else {
            int kk = k - Hn;
            g_Wx[(size_t)(g * 2)     * Hn * In + (size_t)n * In + kk] = hi;
            g_Wx[(size_t)(g * 2 + 1) * Hn * In + (size_t)n * In + kk] = lo;
        }
    }
}
__global__ void prep_x(const float* x) {
    size_t total = (size_t)Mtot * In;
    size_t stride = (size_t)gridDim.x * blockDim.x;
    for (size_t i = blockIdx.x * (size_t)blockDim.x + threadIdx.x; i < total; i += stride) {
        bf16 hi, lo; split2(x[i], hi, lo);
        g_xh[i] = hi; g_xl[i] = lo;
    }
}
__global__ void prep_h(const float* h0) {
    int i = blockIdx.x * blockDim.x + threadIdx.x;
    if (i == 0) g_arrive = 0;                 // reset barrier counter each launch/replay
    if (i < Bn * Hn) {
        float v = h0[i];
        g_h[i] = v;
        bf16 hi, lo; split2(v, hi, lo);
        int row = i >> 10, col = i & (Hn - 1);
        char* p = (char*)g_A1 + aoff(row, col);
        *(bf16*)p = hi;
        *(bf16*)(p + 8192) = lo;
    }
}

// ---------------- x-projection GEMM (3-term split, 128x128 tiles) ----------
#define LDS_PAD 40
#define XT 10240
__device__ __forceinline__ void ldAfrag(uint32_t* a, const bf16* As, int mb, int k0, int lane) {
    int r = lane >> 2, c2 = (lane & 3) * 2;
    a[0] = *(const uint32_t*)(As + (size_t)(mb + r)     * LDS_PAD + k0 + c2);
    a[1] = *(const uint32_t*)(As + (size_t)(mb + r + 8) * LDS_PAD + k0 + c2);
    a[2] = *(const uint32_t*)(As + (size_t)(mb + r)     * LDS_PAD + k0 + 8 + c2);
    a[3] = *(const uint32_t*)(As + (size_t)(mb + r + 8) * LDS_PAD + k0 + 8 + c2);
}
__device__ __forceinline__ void ldBfrag(uint32_t* b, const bf16* Bs, int nb, int k0, int lane) {
    int r = lane >> 2, c2 = (lane & 3) * 2;
    b[0] = *(const uint32_t*)(Bs + (size_t)(nb + r) * LDS_PAD + k0 + c2);
    b[1] = *(const uint32_t*)(Bs + (size_t)(nb + r) * LDS_PAD + k0 + 8 + c2);
}

__global__ void __launch_bounds__(256) xproj_kernel(const float* bz, const float* br, const float* bt) {
    extern __shared__ char xsm[];
    const int gate = blockIdx.x >> 3;
    const int n0 = (blockIdx.x & 7) * 128;
    const int m0 = blockIdx.y * 128;
    const int tid = threadIdx.x, lane = tid & 31, warp = tid >> 5;
    const int wm = (warp & 3) * 32, wn = (warp >> 2) * 64;

    const bf16* Bh0 = g_Wx + (size_t)(gate * 2)     * ((size_t)Hn * In) + (size_t)n0 * In;
    const bf16* Bl0 = g_Wx + (size_t)(gate * 2 + 1) * ((size_t)Hn * In) + (size_t)n0 * In;

    float acc[2][8][4];
    #pragma unroll
    for (int i = 0; i < 2; i++)
        #pragma unroll
        for (int j = 0; j < 8; j++)
            #pragma unroll
            for (int k = 0; k < 4; k++) acc[i][j][k] = 0.f;

    auto issue = [&](int it, int buf) {
        int kk = it * 32;
        #pragma unroll
        for (int j = 0; j < 2; j++) {
            int id = tid + j * 256;
            int r = id >> 2, cg = (id & 3) * 8;
            size_t go = (size_t)r * In + kk + cg;
            char* base = xsm + (size_t)buf * (4 * XT) + (r * LDS_PAD + cg) * 2;
            cp16(base,           g_xh + (size_t)(m0) * In + go);
            cp16(base + XT,      g_xl + (size_t)(m0) * In + go);
            cp16(base + 2 * XT,  Bh0 + go);
            cp16(base + 3 * XT,  Bl0 + go);
        }
    };

    issue(0, 0);
    CP_COMMIT();
    for (int it = 0; it < 32; it++) {
        int buf = it & 1;
        if (it + 1 < 32) { issue(it + 1, buf ^ 1); CP_COMMIT(); CP_WAIT1(); }
        else             { CP_WAIT0(); }
        __syncthreads();
        const bf16* Ah = (const bf16*)(xsm + (size_t)buf * (4 * XT));
        const bf16* Al = (const bf16*)(xsm + (size_t)buf * (4 * XT) + XT);
        const bf16* Bh = (const bf16*)(xsm + (size_t)buf * (4 * XT) + 2 * XT);
        const bf16* Bl = (const bf16*)(xsm + (size_t)buf * (4 * XT) + 3 * XT);
        #pragma unroll
        for (int ks = 0; ks < 32; ks += 16) {
            uint32_t ah[2][4], al[2][4];
            #pragma unroll
            for (int mi = 0; mi < 2; mi++) {
                ldAfrag(ah[mi], Ah, wm + mi * 16, ks, lane);
                ldAfrag(al[mi], Al, wm + mi * 16, ks, lane);
            }
            #pragma unroll
            for (int half = 0; half < 2; half++) {
                uint32_t bhf[4][2], blf[4][2];
                #pragma unroll
                for (int nf = 0; nf < 4; nf++) {
                    ldBfrag(bhf[nf], Bh, wn + half * 32 + nf * 8, ks, lane);
                    ldBfrag(blf[nf], Bl, wn + half * 32 + nf * 8, ks, lane);
                }
                #pragma unroll
                for (int mi = 0; mi < 2; mi++)
                    #pragma unroll
                    for (int nf = 0; nf < 4; nf++) {
                        float* a4 = acc[mi][half * 4 + nf];
                        mma16816(a4, ah[mi], bhf[nf]);
                        mma16816(a4, ah[mi], blf[nf]);
                        mma16816(a4, al[mi], bhf[nf]);
                    }
            }
        }
        __syncthreads();
    }

    const float* bias = (gate == 0) ? bz : ((gate == 1) ? br : bt);
    #pragma unroll
    for (int mi = 0; mi < 2; mi++) {
        #pragma unroll
        for (int nf = 0; nf < 8; nf++) {
            int row = m0 + wm + mi * 16 + (lane >> 2);
            int col = n0 + wn + nf * 8 + (lane & 3) * 2;
            float b0v = bias[col], b1v = bias[col + 1];
            size_t base = (size_t)gate * Mtot * Hn + (size_t)row * Hn + col;
            g_xpre[base]              = acc[mi][nf][0] + b0v;
            g_xpre[base + 1]          = acc[mi][nf][1] + b1v;
            g_xpre[base + 8 * Hn]     = acc[mi][nf][2] + b0v;
            g_xpre[base + 8 * Hn + 1] = acc[mi][nf][3] + b1v;
        }
    }
}

// ---------------- persistent recurrence kernel ----------------
// 64 CTAs x 512 threads. CTA c: ng = c>>2 (N-group), kc = c&3 (K-chunk of 256).
// phase1: cols zr [ng*128,+128), K [kc*256,+256) -> partials g_p1
// phase2: cols t  [ng*64, +64),  K [kc*256,+256) -> partials g_p2
// acts: CTA c owns output cols [c*16,+16), sums 4 partials.
// SMEM: W1 [2 split][128 rows][512B swz] = 131072
//       W2 [2 split][64 rows][512B swz]  =  65536
//       sA [2 buf][2 split][64 rows][128B swz] = 32768
//       mbar[2] = 16
#define W1_OFF 0
#define W2_OFF 131072
#define SA_OFF 196608
#define MB_OFF 229376
#define SMEM_P 229440

__global__ void __launch_bounds__(512, 1) gru_persistent(float* __restrict__ out) {
    extern __shared__ char smem[];
    const int tid = threadIdx.x, lane = tid & 31, warp = tid >> 5;
    const int c = blockIdx.x;
    const int ng = c >> 2, kc = c & 3;
    const int wm = (warp & 3) * 16;      // warp row base (M=64 over 4 row-groups)
    const int cg4 = warp >> 2;           // 0..3: col group

    const uint32_t smem_u32 = (uint32_t)__cvta_generic_to_shared(smem);
    const uint32_t sa_u32 = smem_u32 + SA_OFF;
    const uint32_t mb_u32 = smem_u32 + MB_OFF;

    // ---- load resident weight slices (once) ----
    #pragma unroll
    for (int j = 0; j < 16; j++) {       // W1: 8192 x 16B chunks
        int id = tid + j * 512;
        int split = id >> 12, row = (id >> 5) & 127, ch = id & 31;
        int n = ng * 128 + row;
        int gate = n >> 10, ncol = n & 1023;
        const bf16* src = g_Wh + ((size_t)(gate * 2 + split) << 20)
                          + (size_t)ncol * 1024 + kc * 256 + ch * 8;
        int swz = (ch & 0x18) | ((ch ^ row) & 7);
        cp16(smem + W1_OFF + split * 65536 + row * 512 + swz * 16, src);
    }
    #pragma unroll
    for (int j = 0; j < 8; j++) {        // W2: 4096 chunks
        int id = tid + j * 512;
        int split = id >> 11, row = (id >> 5) & 63, ch = id & 31;
        int n2 = ng * 64 + row;
        const bf16* src = g_Wh + ((size_t)(4 + split) << 20)
                          + (size_t)n2 * 1024 + kc * 256 + ch * 8;
        int swz = (ch & 0x18) | ((ch ^ row) & 7);
        cp16(smem + W2_OFF + split * 32768 + row * 512 + swz * 16, src);
    }
    CP_COMMIT(); CP_WAIT0();
    if (tid == 0) {
        asm volatile("mbarrier.init.shared.b64 [%0], 1;" :: "r"(mb_u32) : "memory");
        asm volatile("mbarrier.init.shared.b64 [%0], 1;" :: "r"(mb_u32 + 8) : "memory");
    }
    __syncthreads();

    // per-lane fragment address components
    const int arow = wm + (lane & 15);                        // A row for ldsm x4
    const int akh  = (lane >> 4) * 8;                         // A k-half
    const int brow_off = ((lane >> 4) << 3) + (lane & 7);     // B ldsm x4 row within 16
    const int bkh  = ((lane >> 3) & 1) * 8;                   // B k-half

    // act element mapping: 2 consecutive cols per thread, 64x16 elems per CTA
    const int e0 = tid * 2;
    const int arw = e0 >> 4;                 // act row (0..63)
    const int ac0 = c * 16 + (e0 & 15);      // act col (even), +1 is sibling

    // one 16KB bulk copy brings k-tile kt (both splits) into sA[buf]
    auto issue_tile = [&](const char* gbase, int kt, int buf) {
        if (tid == 0) {
            uint32_t mb = mb_u32 + buf * 8;
            asm volatile("mbarrier.arrive.expect_tx.shared.b64 _, [%0], %1;"
                         :: "r"(mb), "r"(16384) : "memory");
            asm volatile(
                "cp.async.bulk.shared::cluster.global.mbarrier::complete_tx::bytes [%0], [%1], %2, [%3];"
                :: "r"(sa_u32 + buf * 16384), "l"(gbase + (size_t)kt * 16384),
                   "r"(16384), "r"(mb) : "memory");
        }
    };

    unsigned p0 = 0, p1par = 0;          // mbarrier phase parity per buffer
    unsigned btc = 0;
    for (int t = 0; t < Tn; t++) {
        // ================= phase 1: partial pre_{z,r} =================
        float acc1[2][4][4];
        #pragma unroll
        for (int i = 0; i < 2; i++)
            #pragma unroll
            for (int j = 0; j < 4; j++)
                #pragma unroll
                for (int k = 0; k < 4; k++) acc1[i][j][k] = 0.f;
        issue_tile((const char*)g_A1, kc * 4, 0);

        // prefetch act1 operands (own cols; h stable until act2)
        float xpz[2], xpr[2], hv[2];
        #pragma unroll
        for (int el = 0; el < 2; el++) {
            int col = ac0 + el;
            xpz[el] = g_xpre[((size_t)t * Bn + arw) * Hn + col];
            xpr[el] = g_xpre[((size_t)Mtot + (size_t)t * Bn + arw) * Hn + col];
            hv[el]  = g_h[arw * Hn + col];
        }

        for (int i = 0; i < 4; i++) {
            int buf = i & 1;
            if (i + 1 < 4) issue_tile((const char*)g_A1, kc * 4 + i + 1, buf ^ 1);
            if (buf == 0) { mbar_wait(mb_u32, p0); p0 ^= 1; }
            else         { mbar_wait(mb_u32 + 8, p1par); p1par ^= 1; }
            #pragma unroll
            for (int ks = 0; ks < 4; ks++) {
                int kl = ks * 16 + akh;
                const char* pA = smem + SA_OFF + buf * 16384 + arow * 128
                                 + (((kl >> 3) ^ (arow & 7)) << 4);
                uint32_t ah[4], al[4];
                ldsm4(ah, pA); ldsm4(al, pA + 8192);
                int kg = i * 64 + ks * 16 + bkh;
                int chv = kg >> 3;
                #pragma unroll
                for (int nfp = 0; nfp < 2; nfp++) {
                    int brow = cg4 * 32 + nfp * 16 + brow_off;
                    const char* pB = smem + W1_OFF + brow * 512
                                     + (((chv & 0x18) | ((chv ^ (brow & 7)) & 7)) << 4);
                    uint32_t bh[4], bl[4];
                    ldsm4(bh, pB); ldsm4(bl, pB + 65536);
                    mma16816(acc1[0][nfp * 2],     ah, bh);
                    mma16816(acc1[0][nfp * 2 + 1], ah, bh + 2);
                    mma16816(acc1[1][nfp * 2],     ah, bl);
                    mma16816(acc1[1][nfp * 2 + 1], ah, bl + 2);
                    mma16816(acc1[1][nfp * 2],     al, bh);
                    mma16816(acc1[1][nfp * 2 + 1], al, bh + 2);
                }
            }
            __syncthreads();
        }
        // write phase1 partials
        #pragma unroll
        for (int nf = 0; nf < 4; nf++) {
            #pragma unroll
            for (int ep = 0; ep < 2; ep++) {
                int row = wm + (lane >> 2) + ep * 8;
                int zc = ng * 128 + cg4 * 32 + nf * 8 + (lane & 3) * 2;
                float2 v = make_float2(acc1[0][nf][ep * 2] + acc1[1][nf][ep * 2],
                                       acc1[0][nf][ep * 2 + 1] + acc1[1][nf][ep * 2 + 1]);
                *(float2*)&g_p1[((size_t)(kc * Bn + row)) * HIn + zc] = v;
            }
        }
        btc += GRID_P; grid_bar(btc);

        // ---- act1: z -> g_z ; r -> (r*h) splits into g_A2 ----
        #pragma unroll
        for (int el = 0; el < 2; el++) {
            int col = ac0 + el;
            float zs = 0.f, rs = 0.f;
            #pragma unroll
            for (int q = 0; q < 4; q++) {
                zs += g_p1[((size_t)(q * Bn + arw)) * HIn + col];
                rs += g_p1[((size_t)(q * Bn + arw)) * HIn + 1024 + col];
            }
            float z = sigmoid_f(zs + xpz[el]);
            float r = sigmoid_f(rs + xpr[el]);
            g_z[arw * Hn + col] = z;
            float rh = r * hv[el];
            bf16 hi, lo; split2(rh, hi, lo);
            char* p = (char*)g_A2 + aoff(arw, col);
            *(bf16*)p = hi;
            *(bf16*)(p + 8192) = lo;
        }
        btc += GRID_P; grid_bar(btc);

        // ================= phase 2: partial pre_t =================
        float acc2[2][2][4];
        #pragma unroll
        for (int i = 0; i < 2; i++)
            #pragma unroll
            for (int j = 0; j < 2; j++)
                #pragma unroll
                for (int k = 0; k < 4; k++) acc2[i][j][k] = 0.f;
        issue_tile((const char*)g_A2, kc * 4, 0);

        // prefetch act2 operands (z written before bar2; h stable)
        float xpt[2], zp[2], hp[2];
        #pragma unroll
        for (int el = 0; el < 2; el++) {
            int col = ac0 + el;
            xpt[el] = g_xpre[(2ull * Mtot + (size_t)t * Bn + arw) * Hn + col];
            zp[el] = g_z[arw * Hn + col];
            hp[el] = g_h[arw * Hn + col];
        }

        for (int i = 0; i < 4; i++) {
            int buf = i & 1;
            if (i + 1 < 4) issue_tile((const char*)g_A2, kc * 4 + i + 1, buf ^ 1);
            if (buf == 0) { mbar_wait(mb_u32, p0); p0 ^= 1; }
            else         { mbar_wait(mb_u32 + 8, p1par); p1par ^= 1; }
            #pragma unroll
            for (int ks = 0; ks < 4; ks++) {
                int kl = ks * 16 + akh;
                const char* pA = smem + SA_OFF + buf * 16384 + arow * 128
                                 + (((kl >> 3) ^ (arow & 7)) << 4);
                uint32_t ah[4], al[4];
                ldsm4(ah, pA); ldsm4(al, pA + 8192);
                int kg = i * 64 + ks * 16 + bkh;
                int chv = kg >> 3;
                int brow = cg4 * 16 + brow_off;
                const char* pB = smem + W2_OFF + brow * 512
                                 + (((chv & 0x18) | ((chv ^ (brow & 7)) & 7)) << 4);
                uint32_t bh[4], bl[4];
                ldsm4(bh, pB); ldsm4(bl, pB + 32768);
                mma16816(acc2[0][0], ah, bh);
                mma16816(acc2[0][1], ah, bh + 2);
                mma16816(acc2[1][0], ah, bl);
                mma16816(acc2[1][1], ah, bl + 2);
                mma16816(acc2[1][0], al, bh);
                mma16816(acc2[1][1], al, bh + 2);
            }
            __syncthreads();
        }
        // write phase2 partials
        #pragma unroll
        for (int nf = 0; nf < 2; nf++) {
            #pragma unroll
            for (int ep = 0; ep < 2; ep++) {
                int row = wm + (lane >> 2) + ep * 8;
                int tc = ng * 64 + cg4 * 16 + nf * 8 + (lane & 3) * 2;
                float2 v = make_float2(acc2[0][nf][ep * 2] + acc2[1][nf][ep * 2],
                                       acc2[0][nf][ep * 2 + 1] + acc2[1][nf][ep * 2 + 1]);
                *(float2*)&g_p2[((size_t)(kc * Bn + row)) * Hn + tc] = v;
            }
        }
        btc += GRID_P; grid_bar(btc);

        // ---- act2: h update + output + h splits into g_A1 ----
        #pragma unroll
        for (int el = 0; el < 2; el++) {
            int col = ac0 + el;
            float ps = 0.f;
            #pragma unroll
            for (int q = 0; q < 4; q++)
                ps += g_p2[((size_t)(q * Bn + arw)) * Hn + col];
            float ht = tanh_f(ps + xpt[el]);
            float hn = (1.f - zp[el]) * hp[el] + zp[el] * ht;
            int gi = arw * Hn + col;
            g_h[gi] = hn;
            bf16 hi, lo; split2(hn, hi, lo);
            char* p = (char*)g_A1 + aoff(arw, col);
            *(bf16*)p = hi;
            *(bf16*)(p + 8192) = lo;
            out[(size_t)t * (Bn * Hn) + gi] = hn;
        }
        btc += GRID_P; grid_bar(btc);
    }
}

// ---------------- launch ----------------
extern "C" void kernel_launch(void* const* d_in, const int* in_sizes, int n_in,
                              void* d_out, int out_size) {
    const float* x    = (const float*)d_in[0];
    const float* h0   = (const float*)d_in[1];
    const float* Wz_w = (const float*)d_in[2];
    const float* Wz_b = (const float*)d_in[3];
    const float* Wr_w = (const float*)d_in[4];
    const float* Wr_b = (const float*)d_in[5];
    const float* Wt_w = (const float*)d_in[6];
    const float* Wt_b = (const float*)d_in[7];
    float* out = (float*)d_out;

    cudaFuncSetAttribute(gru_persistent, cudaFuncAttributeMaxDynamicSharedMemorySize, SMEM_P);
    cudaFuncSetAttribute(xproj_kernel, cudaFuncAttributeMaxDynamicSharedMemorySize, 8 * XT);

    prep_weights<<<3072, 256>>>(Wz_w, Wr_w, Wt_w);
    prep_x<<<8192, 256>>>(x);
    prep_h<<<(Bn * Hn + 255) / 256, 256>>>(h0);
    xproj_kernel<<<dim3(24, 256), 256, 8 * XT>>>(Wz_b, Wr_b, Wt_b);
    gru_persistent<<<GRID_P, 512, SMEM_P>>>(out);
}